// round 17
// baseline (speedup 1.0000x reference)
#include <cuda_runtime.h>
#include <cuda_bf16.h>
#include <cstdint>

// ---------------------------------------------------------------------------
// Problem constants
// ---------------------------------------------------------------------------
#define N_NODES 50000
#define N_EDGES 800000
#define IN_CH   128
#define MID_CH  256

// ---------------------------------------------------------------------------
// Scratch (device globals; no dynamic allocation allowed)
// ---------------------------------------------------------------------------
__device__ __align__(16) float g_deg[N_NODES];
__device__ __align__(16) float g_dis[N_NODES];
__device__ __align__(16) float g_h  [(size_t)N_NODES * IN_CH];
__device__ __align__(16) float g_agg[(size_t)N_NODES * IN_CH];
__device__ __align__(16) float g_h1 [(size_t)N_NODES * MID_CH];

// ---------------------------------------------------------------------------
// Degree / norm kernels
// ---------------------------------------------------------------------------
__global__ void k_deg_init()
{
    int i = blockIdx.x * blockDim.x + threadIdx.x;
    if (i < N_NODES) g_deg[i] = 1.0f;
}

__global__ void k_deg_count(const int* __restrict__ dst)
{
    int e = blockIdx.x * blockDim.x + threadIdx.x;
    if (e < N_EDGES) atomicAdd(&g_deg[dst[e]], 1.0f);
}

// dis = rsqrt(deg); also initializes out[i] = b3 (fused, same range)
__global__ void k_dis(float* __restrict__ out, const float* __restrict__ b3)
{
    int i = blockIdx.x * blockDim.x + threadIdx.x;
    if (i < N_NODES) {
        g_dis[i] = rsqrtf(g_deg[i]);
        out[i]   = b3[0];
    }
}

// ---------------------------------------------------------------------------
// TF32 tensor-core GEMM (R7 mainloop, proven): C[M,N] = A[M,K] @ B[K,N]
// BM=BN=128, BK=32, 256 threads = 8 warps (2 x 4), warp tile 64x32,
// mma.sync.aligned.m16n8k8.row.col.f32.tf32.tf32.f32.
// tf32 conversion (cvt.rna) at the global->smem staging stage.
// Smem padding: As rows +4, Bs rows +8 (proven conflict-free).
// EPI: 0 = bias+relu store, 1 = conv (h AND agg=dis^2*h),
//      2 = fused final (relu(acc+bias) dot W3 -> atomicAdd out).
// ---------------------------------------------------------------------------
#define BM 128
#define BN 128
#define BK 32
#define APAD 4
#define BPAD 8

__device__ __forceinline__ float f2tf32(float x)
{
    uint32_t u;
    asm("cvt.rna.tf32.f32 %0, %1;" : "=r"(u) : "f"(x));
    return __uint_as_float(u);
}

template<int N, int K, int EPI, bool BIAS>
__device__ __forceinline__
void gemm_body(const float* __restrict__ A, const float* __restrict__ B,
               const float* __restrict__ bias, float* __restrict__ C,
               const float* __restrict__ W3, float* __restrict__ out, int M)
{
    __shared__ float As[BM][BK + APAD];   // row-major M x K
    __shared__ float Bs[BK][BN + BPAD];   // row-major K x N

    const int tid  = threadIdx.x;
    const int wid  = tid >> 5;
    const int lane = tid & 31;
    const int g    = lane >> 2;   // groupID 0..7
    const int t    = lane & 3;    // threadID_in_group 0..3

    const int warp_m = wid & 1;   // 0..1  -> 64-row slab
    const int warp_n = wid >> 1;  // 0..3  -> 32-col slab

    const int row0 = blockIdx.y * BM;
    const int col0 = blockIdx.x * BN;

    float acc[4][4][4];           // [m-tile][n-tile][c0..c3]
#pragma unroll
    for (int i = 0; i < 4; i++)
#pragma unroll
        for (int j = 0; j < 4; j++)
#pragma unroll
            for (int r = 0; r < 4; r++) acc[i][j][r] = 0.0f;

#pragma unroll 1
    for (int k0 = 0; k0 < K; k0 += BK) {
        // --- A tile: 128x32 = 1024 float4, 4 per thread (tf32 convert) ---
#pragma unroll
        for (int it = 0; it < 4; it++) {
            int idx = tid + it * 256;        // 0..1023
            int r   = idx >> 3;              // 8 float4 per 32-float row
            int c4  = idx & 7;
            int gr  = row0 + r;
            float4 v = make_float4(0.f, 0.f, 0.f, 0.f);
            if (gr < M)
                v = *reinterpret_cast<const float4*>(A + (size_t)gr * K + k0 + c4 * 4);
            float* dstp = &As[r][c4 * 4];
            dstp[0] = f2tf32(v.x); dstp[1] = f2tf32(v.y);
            dstp[2] = f2tf32(v.z); dstp[3] = f2tf32(v.w);
        }
        // --- B tile: 32x128 = 1024 float4, 4 per thread (tf32 convert) ---
#pragma unroll
        for (int it = 0; it < 4; it++) {
            int idx = tid + it * 256;
            int r   = idx >> 5;              // 32 float4 per 128-float row
            int c4  = idx & 31;
            float4 v = *reinterpret_cast<const float4*>(
                B + (size_t)(k0 + r) * N + col0 + c4 * 4);
            float* dstp = &Bs[r][c4 * 4];
            dstp[0] = f2tf32(v.x); dstp[1] = f2tf32(v.y);
            dstp[2] = f2tf32(v.z); dstp[3] = f2tf32(v.w);
        }
        __syncthreads();

#pragma unroll
        for (int kk = 0; kk < BK; kk += 8) {
            uint32_t af[4][4];
#pragma unroll
            for (int mt = 0; mt < 4; mt++) {
                int rb = warp_m * 64 + mt * 16;
                af[mt][0] = __float_as_uint(As[rb + g    ][kk + t    ]);
                af[mt][1] = __float_as_uint(As[rb + g + 8][kk + t    ]);
                af[mt][2] = __float_as_uint(As[rb + g    ][kk + t + 4]);
                af[mt][3] = __float_as_uint(As[rb + g + 8][kk + t + 4]);
            }
            uint32_t bf[4][2];
#pragma unroll
            for (int nt = 0; nt < 4; nt++) {
                int cb = warp_n * 32 + nt * 8 + g;
                bf[nt][0] = __float_as_uint(Bs[kk + t    ][cb]);
                bf[nt][1] = __float_as_uint(Bs[kk + t + 4][cb]);
            }
#pragma unroll
            for (int mt = 0; mt < 4; mt++)
#pragma unroll
                for (int nt = 0; nt < 4; nt++) {
                    asm volatile(
                        "mma.sync.aligned.m16n8k8.row.col.f32.tf32.tf32.f32 "
                        "{%0,%1,%2,%3}, {%4,%5,%6,%7}, {%8,%9}, {%0,%1,%2,%3};"
                        : "+f"(acc[mt][nt][0]), "+f"(acc[mt][nt][1]),
                          "+f"(acc[mt][nt][2]), "+f"(acc[mt][nt][3])
                        : "r"(af[mt][0]), "r"(af[mt][1]),
                          "r"(af[mt][2]), "r"(af[mt][3]),
                          "r"(bf[nt][0]), "r"(bf[nt][1]));
                }
        }
        __syncthreads();
    }

    // ---- epilogue: c0/c1 -> (row=g, cols 2t,2t+1), c2/c3 -> row=g+8 ----
#pragma unroll
    for (int mt = 0; mt < 4; mt++) {
#pragma unroll
        for (int half = 0; half < 2; half++) {
            int gr = row0 + warp_m * 64 + mt * 16 + g + half * 8;
            if (gr >= M) continue;

            if (EPI == 2) {
                // fused final: s = sum relu(acc+bias)*W3 -> atomicAdd out[gr]
                float s = 0.0f;
#pragma unroll
                for (int nt = 0; nt < 4; nt++) {
                    int gc = col0 + warp_n * 32 + nt * 8 + t * 2;
                    float v0 = acc[mt][nt][half * 2 + 0] + bias[gc];
                    float v1 = acc[mt][nt][half * 2 + 1] + bias[gc + 1];
                    v0 = fmaxf(v0, 0.0f);
                    v1 = fmaxf(v1, 0.0f);
                    s = fmaf(v0, __ldg(W3 + gc), s);
                    s = fmaf(v1, __ldg(W3 + gc + 1), s);
                }
                atomicAdd(out + gr, s);
            } else if (EPI == 1) {
                // conv: store h and agg = dis^2 * h
                float dsq = g_dis[gr];
                dsq = dsq * dsq;
#pragma unroll
                for (int nt = 0; nt < 4; nt++) {
                    int gc = col0 + warp_n * 32 + nt * 8 + t * 2;
                    float v0 = acc[mt][nt][half * 2 + 0];
                    float v1 = acc[mt][nt][half * 2 + 1];
                    *reinterpret_cast<float2*>(C + (size_t)gr * N + gc) =
                        make_float2(v0, v1);
                    *reinterpret_cast<float2*>(g_agg + (size_t)gr * N + gc) =
                        make_float2(dsq * v0, dsq * v1);
                }
            } else {
#pragma unroll
                for (int nt = 0; nt < 4; nt++) {
                    int gc = col0 + warp_n * 32 + nt * 8 + t * 2;
                    float v0 = acc[mt][nt][half * 2 + 0];
                    float v1 = acc[mt][nt][half * 2 + 1];
                    if (BIAS) { v0 += bias[gc]; v1 += bias[gc + 1]; }
                    v0 = fmaxf(v0, 0.0f);
                    v1 = fmaxf(v1, 0.0f);
                    *reinterpret_cast<float2*>(C + (size_t)gr * N + gc) =
                        make_float2(v0, v1);
                }
            }
        }
    }
}

__global__ __launch_bounds__(256)
void k_gemm_conv(const float* __restrict__ x, const float* __restrict__ W)
{
    gemm_body<IN_CH, IN_CH, 1, false>(x, W, nullptr, g_h, nullptr, nullptr, N_NODES);
}

__global__ __launch_bounds__(256)
void k_gemm_mlp1(const float* __restrict__ W1, const float* __restrict__ b1)
{
    gemm_body<MID_CH, IN_CH, 0, true>(g_h, W1, b1, g_h1, nullptr, nullptr, N_NODES);
}

__global__ __launch_bounds__(256)
void k_gemm_mlp2(const float* __restrict__ W2, const float* __restrict__ b2,
                 const float* __restrict__ W3, float* __restrict__ out)
{
    gemm_body<MID_CH, MID_CH, 2, true>(g_h1, W2, b2, nullptr, W3, out, N_NODES);
}

// ---------------------------------------------------------------------------
// Edge scatter: agg[dst,:] += dis[src]*dis[dst] * h[src,:]
// One warp per edge, lane = 4 channels, vector RED.
// ---------------------------------------------------------------------------
__global__ __launch_bounds__(256)
void k_scatter(const int* __restrict__ src, const int* __restrict__ dst)
{
    int e = blockIdx.x * 8 + (threadIdx.x >> 5);
    if (e >= N_EDGES) return;
    int lane = threadIdx.x & 31;

    int s = __ldg(src + e);
    int d = __ldg(dst + e);
    float nrm = g_dis[s] * g_dis[d];

    float4 v = reinterpret_cast<const float4*>(g_h + (size_t)s * IN_CH)[lane];
    v.x *= nrm; v.y *= nrm; v.z *= nrm; v.w *= nrm;

    float* ag = g_agg + (size_t)d * IN_CH + lane * 4;
    asm volatile("red.global.add.v4.f32 [%0], {%1, %2, %3, %4};"
                 :: "l"(ag), "f"(v.x), "f"(v.y), "f"(v.z), "f"(v.w)
                 : "memory");
}

// ---------------------------------------------------------------------------
// Post-conv epilogue: h = relu(agg + b_conv) + x
// ---------------------------------------------------------------------------
__global__ void k_postconv(const float* __restrict__ x, const float* __restrict__ b_conv)
{
    size_t i = (size_t)blockIdx.x * blockDim.x + threadIdx.x;   // float4 index
    if (i >= (size_t)N_NODES * IN_CH / 4) return;
    int c4 = (int)(i & 31);
    float4 b  = reinterpret_cast<const float4*>(b_conv)[c4];
    float4 a  = reinterpret_cast<const float4*>(g_agg)[i];
    float4 xr = reinterpret_cast<const float4*>(x)[i];
    float4 o;
    o.x = fmaxf(a.x + b.x, 0.0f) + xr.x;
    o.y = fmaxf(a.y + b.y, 0.0f) + xr.y;
    o.z = fmaxf(a.z + b.z, 0.0f) + xr.z;
    o.w = fmaxf(a.w + b.w, 0.0f) + xr.w;
    reinterpret_cast<float4*>(g_h)[i] = o;
}

// ---------------------------------------------------------------------------
// kernel_launch
// ---------------------------------------------------------------------------
extern "C" void kernel_launch(void* const* d_in, const int* in_sizes, int n_in,
                              void* d_out, int out_size)
{
    const float* x      = (const float*)d_in[0];
    const int*   eidx   = (const int*)d_in[1];     // int32 (JAX x64 disabled)
    const float* W_conv = (const float*)d_in[2];
    const float* b_conv = (const float*)d_in[3];
    const float* W1     = (const float*)d_in[4];
    const float* b1     = (const float*)d_in[5];
    const float* W2     = (const float*)d_in[6];
    const float* b2     = (const float*)d_in[7];
    const float* W3     = (const float*)d_in[8];
    const float* b3     = (const float*)d_in[9];
    float*       out    = (float*)d_out;

    const int* e_src = eidx;
    const int* e_dst = eidx + N_EDGES;

    const int MT = (N_NODES + BM - 1) / BM;   // 391 M-tiles

    // degree + norm (k_dis also initializes out = b3)
    k_deg_init<<<(N_NODES + 255) / 256, 256>>>();
    k_deg_count<<<(N_EDGES + 255) / 256, 256>>>(e_dst);
    k_dis<<<(N_NODES + 255) / 256, 256>>>(out, b3);

    // h = x @ W_conv ; agg = dis^2 * h   (selfloop fused into epilogue)
    k_gemm_conv<<<dim3(IN_CH / BN, MT), 256>>>(x, W_conv);

    // edge scatter into agg
    k_scatter<<<(N_EDGES + 7) / 8, 256>>>(e_src, e_dst);

    // h = relu(agg + b_conv) + x
    {
        size_t tot4 = (size_t)N_NODES * IN_CH / 4;
        k_postconv<<<(unsigned)((tot4 + 255) / 256), 256>>>(x, b_conv);
    }

    // h1 = relu(h @ W1 + b1)
    k_gemm_mlp1<<<dim3(MID_CH / BN, MT), 256>>>(W1, b1);

    // out = relu(h1 @ W2 + b2) @ W3 + b3   (final fused into mlp2 epilogue)
    k_gemm_mlp2<<<dim3(MID_CH / BN, MT), 256>>>(W2, b2, W3, out);
}